// round 12
// baseline (speedup 1.0000x reference)
#include <cuda_runtime.h>
#include <cuda_fp16.h>
#include <cstdint>

// ---------------- problem constants ----------------
#define M_TOK   128          // B*S = 8*16 tokens
#define K_DIM   4096
#define N_OUT   16384
#define N_TILE  64
#define K_TILE  64
#define NK      (K_DIM / K_TILE)   // 64
#define THREADS 256          // warps 0-3 consumers, 4-7 producers
#define STAGES  4

// ---------------- smem layout ----------------
#define OFF_BIAS 0                          // 64 floats
#define OFF_MBAR 256                        // full[s]@+16s, empty[s]@+16s+8
#define OFF_STG  1024
#define A_BYTES  (M_TOK * K_TILE * 2)       // 16384 fp16 swizzled (pitch 128B)
#define B_BYTES  (N_TILE * K_TILE * 2)      // 8192  fp16 swizzled
#define STG_BYTES (A_BYTES + B_BYTES)       // 24576
#define SMEM_BYTES (OFF_STG + STAGES * STG_BYTES)   // 99328 (x2 CTAs = 194KB)

// ---------------- device scratch ----------------
// x as fp16, PRE-SWIZZLED per K-tile: [NK][128 rows][8 x 16B], row pitch 128B.
// Each 16KB K-tile block is CONTIGUOUS -> single cp.async.bulk per stage.
__device__ uint4  g_x16[M_TOK * K_DIM / 8];
__device__ float  g_xsum[M_TOK];              // per-token sum (zero-point term)

// ---------------- helpers ----------------
__device__ __forceinline__ uint32_t smem_to_u32(const void* p) {
    uint32_t a;
    asm("{ .reg .u64 t; cvta.to.shared.u64 t, %1; cvt.u32.u64 %0, t; }" : "=r"(a) : "l"(p));
    return a;
}
#define SW128(o) ((o) ^ (((o) >> 3) & 0x70))

#define MBARRIER_INIT(addr, cnt) \
    asm volatile("mbarrier.init.shared.b64 [%0], %1;" :: "r"((uint32_t)(addr)), "r"((uint32_t)(cnt)) : "memory")
#define MBARRIER_ARRIVE(addr) \
    asm volatile("mbarrier.arrive.release.cta.shared.b64 _, [%0];" :: "r"((uint32_t)(addr)) : "memory")
// Arriving expect_tx: registers tx-count, then counts as ONE arrive.
#define MBARRIER_ARRIVE_EXPECT_TX(addr, tx) \
    asm volatile("mbarrier.arrive.expect_tx.release.cta.shared::cta.b64 _, [%0], %1;" \
                 :: "r"((uint32_t)(addr)), "r"((uint32_t)(tx)) : "memory")
// Bulk async copy gmem -> smem, completion via mbarrier complete_tx.
#define CP_ASYNC_BULK(dst, src, bytes, mbar) \
    asm volatile("cp.async.bulk.shared::cluster.global.mbarrier::complete_tx::bytes [%0], [%1], %2, [%3];" \
                 :: "r"((uint32_t)(dst)), "l"(src), "r"((uint32_t)(bytes)), "r"((uint32_t)(mbar)) : "memory")

#define MBARRIER_WAIT_PARITY(addr, par) do {                                          \
    uint32_t _mbar = (uint32_t)(addr);                                                \
    uint32_t _p = (uint32_t)(par);                                                    \
    uint32_t _done;                                                                   \
    asm volatile("{\n\t.reg .pred p;\n\t"                                             \
        "mbarrier.try_wait.parity.acquire.cta.shared::cta.b64 p, [%1], %2;\n\t"       \
        "selp.b32 %0, 1, 0, p;\n\t}" : "=r"(_done) : "r"(_mbar), "r"(_p) : "memory"); \
    if (!_done) {                                                                     \
        asm volatile("{\n\t.reg .pred P1;\n\t"                                        \
            "WL_%=:\n\t"                                                              \
            "mbarrier.try_wait.parity.acquire.cta.shared::cta.b64 P1, [%0], %1, 0x989680;\n\t" \
            "@P1 bra.uni WD_%=;\n\t"                                                  \
            "bra.uni WL_%=;\n\t"                                                      \
            "WD_%=:\n\t}" :: "r"(_mbar), "r"(_p) : "memory");                         \
    }                                                                                 \
} while (0)

__device__ __forceinline__ void ldsm_x4(uint32_t& r0, uint32_t& r1, uint32_t& r2,
                                        uint32_t& r3, uint32_t addr) {
    asm volatile("ldmatrix.sync.aligned.m8n8.x4.shared.b16 {%0,%1,%2,%3}, [%4];"
                 : "=r"(r0), "=r"(r1), "=r"(r2), "=r"(r3) : "r"(addr));
}
__device__ __forceinline__ void mma16816(float* d, const uint32_t* a, const uint32_t* b) {
    asm volatile(
        "mma.sync.aligned.m16n8k16.row.col.f32.f16.f16.f32 "
        "{%0,%1,%2,%3}, {%4,%5,%6,%7}, {%8,%9}, {%0,%1,%2,%3};"
        : "+f"(d[0]), "+f"(d[1]), "+f"(d[2]), "+f"(d[3])
        : "r"(a[0]), "r"(a[1]), "r"(a[2]), "r"(a[3]), "r"(b[0]), "r"(b[1]));
}

// ---------------- prep kernel: x f32 -> f16 (pre-swizzled tiles), per-row sums ----------------
__global__ void __launch_bounds__(256) sqlin_prep(const float* __restrict__ x) {
    const int m = blockIdx.x;
    const int tid = threadIdx.x;
    char* xb = reinterpret_cast<char*>(g_x16);
    float s = 0.0f;
    #pragma unroll
    for (int j = 0; j < 2; j++) {
        const int idx = tid + 256 * j;           // granule id: 512 = NK*8 per row
        const int kt = idx >> 3, c = idx & 7;
        const float4* src = reinterpret_cast<const float4*>(
            x + (size_t)m * K_DIM + kt * 64 + c * 8);
        float4 v0 = src[0], v1 = src[1];
        s += v0.x + v0.y + v0.z + v0.w + v1.x + v1.y + v1.z + v1.w;
        __half2 h0 = __floats2half2_rn(v0.x, v0.y);
        __half2 h1 = __floats2half2_rn(v0.z, v0.w);
        __half2 h2 = __floats2half2_rn(v1.x, v1.y);
        __half2 h3 = __floats2half2_rn(v1.z, v1.w);
        uint4 pk;
        pk.x = *reinterpret_cast<const uint32_t*>(&h0);
        pk.y = *reinterpret_cast<const uint32_t*>(&h1);
        pk.z = *reinterpret_cast<const uint32_t*>(&h2);
        pk.w = *reinterpret_cast<const uint32_t*>(&h3);
        uint32_t off = (uint32_t)kt * A_BYTES + SW128((uint32_t)(m * 128 + c * 16));
        *reinterpret_cast<uint4*>(xb + off) = pk;
    }
    #pragma unroll
    for (int o = 16; o > 0; o >>= 1) s += __shfl_xor_sync(0xFFFFFFFFu, s, o);
    __shared__ float red[8];
    if ((tid & 31) == 0) red[tid >> 5] = s;
    __syncthreads();
    if (tid == 0) {
        float t = 0.0f;
        #pragma unroll
        for (int i = 0; i < 8; i++) t += red[i];
        g_xsum[m] = t;
    }
}

// ---------------- main GEMM (warp-specialized, bulk-copy A, folded swizzle) ----------------
__global__ void __launch_bounds__(THREADS, 2)
sqlin_gemm(const int* __restrict__ w, const float* __restrict__ scale_p,
           const float* __restrict__ zp_p, const float* __restrict__ bias,
           float* __restrict__ out) {
    extern __shared__ char smem[];
    const uint32_t sb = smem_to_u32(smem);
    const int tid = threadIdx.x, wid = tid >> 5, lane = tid & 31;
    const int n0 = blockIdx.x * N_TILE;

    if (tid == 0) {
        #pragma unroll
        for (int s = 0; s < STAGES; s++) {
            // full: 4 elected producer-warp arrives + 1 expect_tx-arrive = 5;
            //       plus A_BYTES of tx from the bulk copy.
            MBARRIER_INIT(sb + OFF_MBAR + s * 16, 5);
            MBARRIER_INIT(sb + OFF_MBAR + s * 16 + 8, 4);   // empty: 4 consumer warps
        }
    }
    if (tid < N_TILE)
        reinterpret_cast<float*>(smem + OFF_BIAS)[tid] = bias[n0 + tid];
    __syncthreads();

    if (wid >= 4) {
        // ================= PRODUCER (4 warps): bulk A + convert B =================
        const int ptid = tid - 128;
        const uint4* wv = reinterpret_cast<const uint4*>(w);
        const char* xsrc = reinterpret_cast<const char*>(g_x16);

        // Folded-swizzle STS base: row = (ptid>>4) + 8j, c = ptid&15 (const).
        const uint32_t sts0 = (uint32_t)(((ptid >> 4) * 128) +
                              (((ptid & 15) * 8) ^ ((((ptid >> 4) & 7)) << 4)));

        uint4 rb[2][8];
        #pragma unroll
        for (int j = 0; j < 8; j++) {                 // prefetch B for kt=0
            int idx = ptid + 128 * j;
            int row = idx >> 4, c = idx & 15;
            rb[0][j] = wv[(size_t)(n0 + row) * (K_DIM / 4) + c];
        }

        #pragma unroll 2
        for (int kt = 0; kt < NK; kt++) {
            const int s = kt & (STAGES - 1);
            const int r = kt >> 2;

            // hoist next B LDGs ABOVE the empty wait (latency overlap)
            if (kt + 1 < NK) {
                #pragma unroll
                for (int j = 0; j < 8; j++) {
                    int idx = ptid + 128 * j;
                    int row = idx >> 4, c = idx & 15;
                    rb[(kt + 1) & 1][j] =
                        wv[(size_t)(n0 + row) * (K_DIM / 4) + (size_t)(kt + 1) * (K_TILE / 4) + c];
                }
            }

            if (r >= 1)   // stage free when round r-1 consumers released it
                MBARRIER_WAIT_PARITY(sb + OFF_MBAR + s * 16 + 8, (r - 1) & 1);

            const uint32_t aB = sb + OFF_STG + s * STG_BYTES;
            // A: one bulk async copy of the contiguous pre-swizzled 16KB tile
            if (wid == 4 && lane == 0) {
                MBARRIER_ARRIVE_EXPECT_TX(sb + OFF_MBAR + s * 16, A_BYTES);
                CP_ASYNC_BULK(aB, xsrc + (size_t)kt * A_BYTES, A_BYTES,
                              sb + OFF_MBAR + s * 16);
            }

            // B: convert int32 -> fp16, STS at folded-swizzle addresses
            const uint32_t bS = aB + A_BYTES + sts0;
            #pragma unroll
            for (int j = 0; j < 8; j++) {
                const int* v = reinterpret_cast<const int*>(&rb[kt & 1][j]);
                __half2 h01 = __halves2half2(__int2half_rn(v[0]), __int2half_rn(v[1]));
                __half2 h23 = __halves2half2(__int2half_rn(v[2]), __int2half_rn(v[3]));
                uint2 pk;
                pk.x = *reinterpret_cast<const uint32_t*>(&h01);
                pk.y = *reinterpret_cast<const uint32_t*>(&h23);
                asm volatile("st.shared.v2.b32 [%0], {%1, %2};"
                             :: "r"(bS + (uint32_t)(j * 1024)), "r"(pk.x), "r"(pk.y) : "memory");
            }
            __syncwarp();
            if (lane == 0) MBARRIER_ARRIVE(sb + OFF_MBAR + s * 16);   // full (release)
        }
    } else {
        // ================= CONSUMER (4 warps, 2x2 grid of 64x32 tiles) =================
        const int warp_m = wid & 1, warp_n = wid >> 1;
        const int fr = lane & 15, fs = lane >> 4;

        // Folded swizzle: SW128(row*128 + x) = row*128 + (x ^ ((fr&7)<<4)).
        const uint32_t kmask = (uint32_t)((fr & 7) << 4);
        uint32_t koff[4];
        #pragma unroll
        for (int ks = 0; ks < 4; ks++)
            koff[ks] = ((uint32_t)(ks * 32 + fs * 16)) ^ kmask;
        const uint32_t aRow = (uint32_t)((warp_m * 64 + fr) * 128);   // + mt*2048
        const uint32_t bRow = (uint32_t)((warp_n * 32 + fr) * 128);   // + bt*2048

        float acc[4][4][4];
        #pragma unroll
        for (int i = 0; i < 4; i++)
            #pragma unroll
            for (int j = 0; j < 4; j++)
                #pragma unroll
                for (int k = 0; k < 4; k++) acc[i][j][k] = 0.0f;

        for (int kt = 0; kt < NK; kt++) {
            const int s = kt & (STAGES - 1);
            const int r = kt >> 2;
            MBARRIER_WAIT_PARITY(sb + OFF_MBAR + s * 16, r & 1);   // wait full (acquire)

            const uint32_t aB = sb + OFF_STG + s * STG_BYTES + aRow;
            const uint32_t bB = sb + OFF_STG + s * STG_BYTES + A_BYTES + bRow;
            #pragma unroll
            for (int ks = 0; ks < 4; ks++) {
                const uint32_t aK = aB + koff[ks];
                const uint32_t bK = bB + koff[ks];
                uint32_t a[4][4], b[2][4];
                #pragma unroll
                for (int mt = 0; mt < 4; mt++)
                    ldsm_x4(a[mt][0], a[mt][1], a[mt][2], a[mt][3], aK + mt * 2048);
                #pragma unroll
                for (int bt = 0; bt < 2; bt++)
                    ldsm_x4(b[bt][0], b[bt][1], b[bt][2], b[bt][3], bK + bt * 2048);
                #pragma unroll
                for (int mt = 0; mt < 4; mt++)
                    #pragma unroll
                    for (int nt = 0; nt < 4; nt++) {
                        uint32_t bf[2] = { b[nt >> 1][nt & 1], b[nt >> 1][(nt & 1) + 2] };
                        mma16816(acc[mt][nt], a[mt], bf);
                    }
            }
            __syncwarp();
            if (lane == 0) MBARRIER_ARRIVE(sb + OFF_MBAR + s * 16 + 8);   // empty
        }

        // ---------------- epilogue ----------------
        const float sc  = *scale_p;
        const float zpv = *zp_p;
        const int qrow = lane >> 2;
        const int qcol = (lane & 3) * 2;
        const float* bs = reinterpret_cast<const float*>(smem + OFF_BIAS);

        #pragma unroll
        for (int mt = 0; mt < 4; mt++) {
            const int m0 = warp_m * 64 + mt * 16 + qrow;
            const float corr0 = sc * zpv * g_xsum[m0];
            const float corr8 = sc * zpv * g_xsum[m0 + 8];
            #pragma unroll
            for (int nt = 0; nt < 4; nt++) {
                const int n = warp_n * 32 + nt * 8 + qcol;
                const float b0 = bs[n], b1 = bs[n + 1];
                float2 v0, v1;
                v0.x = fmaf(sc, acc[mt][nt][0], b0 - corr0);
                v0.y = fmaf(sc, acc[mt][nt][1], b1 - corr0);
                v1.x = fmaf(sc, acc[mt][nt][2], b0 - corr8);
                v1.y = fmaf(sc, acc[mt][nt][3], b1 - corr8);
                *reinterpret_cast<float2*>(out + (size_t)m0 * N_OUT + n0 + n) = v0;
                *reinterpret_cast<float2*>(out + (size_t)(m0 + 8) * N_OUT + n0 + n) = v1;
            }
        }
    }
}

// ---------------- launch ----------------
extern "C" void kernel_launch(void* const* d_in, const int* in_sizes, int n_in,
                              void* d_out, int out_size) {
    (void)in_sizes; (void)n_in; (void)out_size;
    const float* x     = (const float*)d_in[0];
    const int*   w     = (const int*)  d_in[1];
    const float* scale = (const float*)d_in[2];
    const float* zp    = (const float*)d_in[3];
    const float* bias  = (const float*)d_in[4];
    float* out = (float*)d_out;

    cudaFuncSetAttribute(sqlin_gemm, cudaFuncAttributeMaxDynamicSharedMemorySize, SMEM_BYTES);

    sqlin_prep<<<M_TOK, 256>>>(x);
    sqlin_gemm<<<N_OUT / N_TILE, THREADS, SMEM_BYTES>>>(w, scale, zp, bias, out);
}

// round 15
// speedup vs baseline: 1.0024x; 1.0024x over previous
#include <cuda_runtime.h>
#include <cuda_fp16.h>
#include <cstdint>

// ---------------- problem constants ----------------
#define M_TOK   128          // B*S = 8*16 tokens
#define K_DIM   4096
#define N_OUT   16384
#define N_TILE  64
#define K_TILE  64
#define NK      (K_DIM / K_TILE)   // 64
#define THREADS 256          // warps 0-3 consumers, 4-7 producers
#define STAGES  4

// ---------------- smem layout ----------------
#define OFF_BIAS 0                          // 64 floats
#define OFF_MBAR 256                        // full[s]@+16s, empty[s]@+16s+8
#define OFF_STG  1024
#define A_BYTES  (M_TOK * K_TILE * 2)       // 16384 fp16 swizzled (pitch 128B)
#define B_BYTES  (N_TILE * K_TILE * 2)      // 8192  fp16 swizzled
#define STG_BYTES (A_BYTES + B_BYTES)       // 24576
#define SMEM_BYTES (OFF_STG + STAGES * STG_BYTES)   // 99328 (x2 CTAs = 194KB)

// ---------------- device scratch ----------------
// x as fp16, PRE-SWIZZLED per K-tile: [NK][128 rows][8 x 16B], row pitch 128B
__device__ uint4  g_x16[M_TOK * K_DIM / 8];
__device__ float  g_xsum[M_TOK];              // per-token sum (zero-point term)

// ---------------- helpers ----------------
__device__ __forceinline__ uint32_t smem_to_u32(const void* p) {
    uint32_t a;
    asm("{ .reg .u64 t; cvta.to.shared.u64 t, %1; cvt.u32.u64 %0, t; }" : "=r"(a) : "l"(p));
    return a;
}
#define SW128(o) ((o) ^ (((o) >> 3) & 0x70))

__device__ __forceinline__ void cp_async16(uint32_t dst, const void* src) {
    asm volatile("cp.async.cg.shared.global [%0], [%1], 16;" :: "r"(dst), "l"(src));
}
// Default (non-.noinc) form: SELF-BALANCING — net-zero vs init count.
#define CP_ASYNC_MBAR_ARRIVE(addr) \
    asm volatile("cp.async.mbarrier.arrive.shared.b64 [%0];" :: "r"((uint32_t)(addr)) : "memory")

#define MBARRIER_INIT(addr, cnt) \
    asm volatile("mbarrier.init.shared.b64 [%0], %1;" :: "r"((uint32_t)(addr)), "r"((uint32_t)(cnt)) : "memory")
#define MBARRIER_ARRIVE(addr) \
    asm volatile("mbarrier.arrive.release.cta.shared.b64 _, [%0];" :: "r"((uint32_t)(addr)) : "memory")
#define MBARRIER_WAIT_PARITY(addr, par) do {                                          \
    uint32_t _mbar = (uint32_t)(addr);                                                \
    uint32_t _p = (uint32_t)(par);                                                    \
    uint32_t _done;                                                                   \
    asm volatile("{\n\t.reg .pred p;\n\t"                                             \
        "mbarrier.try_wait.parity.acquire.cta.shared::cta.b64 p, [%1], %2;\n\t"       \
        "selp.b32 %0, 1, 0, p;\n\t}" : "=r"(_done) : "r"(_mbar), "r"(_p) : "memory"); \
    if (!_done) {                                                                     \
        asm volatile("{\n\t.reg .pred P1;\n\t"                                        \
            "WL_%=:\n\t"                                                              \
            "mbarrier.try_wait.parity.acquire.cta.shared::cta.b64 P1, [%0], %1, 0x989680;\n\t" \
            "@P1 bra.uni WD_%=;\n\t"                                                  \
            "bra.uni WL_%=;\n\t"                                                      \
            "WD_%=:\n\t}" :: "r"(_mbar), "r"(_p) : "memory");                         \
    }                                                                                 \
} while (0)

__device__ __forceinline__ void ldsm_x4(uint32_t& r0, uint32_t& r1, uint32_t& r2,
                                        uint32_t& r3, uint32_t addr) {
    asm volatile("ldmatrix.sync.aligned.m8n8.x4.shared.b16 {%0,%1,%2,%3}, [%4];"
                 : "=r"(r0), "=r"(r1), "=r"(r2), "=r"(r3) : "r"(addr));
}
__device__ __forceinline__ void mma16816(float* d, const uint32_t* a, const uint32_t* b) {
    asm volatile(
        "mma.sync.aligned.m16n8k16.row.col.f32.f16.f16.f32 "
        "{%0,%1,%2,%3}, {%4,%5,%6,%7}, {%8,%9}, {%0,%1,%2,%3};"
        : "+f"(d[0]), "+f"(d[1]), "+f"(d[2]), "+f"(d[3])
        : "r"(a[0]), "r"(a[1]), "r"(a[2]), "r"(a[3]), "r"(b[0]), "r"(b[1]));
}

// ---------------- prep kernel: x f32 -> f16 (pre-swizzled tiles), per-row sums ----------------
__global__ void __launch_bounds__(256) sqlin_prep(const float* __restrict__ x) {
    // PDL: let the dependent GEMM kernel start launching now; its
    // griddepcontrol.wait still blocks until all our writes are visible.
    asm volatile("griddepcontrol.launch_dependents;");

    const int m = blockIdx.x;
    const int tid = threadIdx.x;
    char* xb = reinterpret_cast<char*>(g_x16);
    float s = 0.0f;
    #pragma unroll
    for (int j = 0; j < 2; j++) {
        const int idx = tid + 256 * j;           // granule id: 512 = NK*8 per row
        const int kt = idx >> 3, c = idx & 7;
        const float4* src = reinterpret_cast<const float4*>(
            x + (size_t)m * K_DIM + kt * 64 + c * 8);
        float4 v0 = src[0], v1 = src[1];
        s += v0.x + v0.y + v0.z + v0.w + v1.x + v1.y + v1.z + v1.w;
        __half2 h0 = __floats2half2_rn(v0.x, v0.y);
        __half2 h1 = __floats2half2_rn(v0.z, v0.w);
        __half2 h2 = __floats2half2_rn(v1.x, v1.y);
        __half2 h3 = __floats2half2_rn(v1.z, v1.w);
        uint4 pk;
        pk.x = *reinterpret_cast<const uint32_t*>(&h0);
        pk.y = *reinterpret_cast<const uint32_t*>(&h1);
        pk.z = *reinterpret_cast<const uint32_t*>(&h2);
        pk.w = *reinterpret_cast<const uint32_t*>(&h3);
        uint32_t off = (uint32_t)kt * A_BYTES + SW128((uint32_t)(m * 128 + c * 16));
        *reinterpret_cast<uint4*>(xb + off) = pk;
    }
    #pragma unroll
    for (int o = 16; o > 0; o >>= 1) s += __shfl_xor_sync(0xFFFFFFFFu, s, o);
    __shared__ float red[8];
    if ((tid & 31) == 0) red[tid >> 5] = s;
    __syncthreads();
    if (tid == 0) {
        float t = 0.0f;
        #pragma unroll
        for (int i = 0; i < 8; i++) t += red[i];
        g_xsum[m] = t;
    }
}

// ---------------- main GEMM (warp-specialized, folded swizzle, B-frag pipeline) ----------------
__global__ void __launch_bounds__(THREADS, 2)
sqlin_gemm(const int* __restrict__ w, const float* __restrict__ scale_p,
           const float* __restrict__ zp_p, const float* __restrict__ bias,
           float* __restrict__ out) {
    // PDL: wait until prep's writes (g_x16, g_xsum) are visible.
    asm volatile("griddepcontrol.wait;");

    extern __shared__ char smem[];
    const uint32_t sb = smem_to_u32(smem);
    const int tid = threadIdx.x, wid = tid >> 5, lane = tid & 31;
    const int n0 = blockIdx.x * N_TILE;

    if (tid == 0) {
        #pragma unroll
        for (int s = 0; s < STAGES; s++) {
            MBARRIER_INIT(sb + OFF_MBAR + s * 16, 4);       // full: 4 elected producer warps
            MBARRIER_INIT(sb + OFF_MBAR + s * 16 + 8, 4);   // empty: 4 elected consumer warps
        }
    }
    if (tid < N_TILE)
        reinterpret_cast<float*>(smem + OFF_BIAS)[tid] = bias[n0 + tid];
    __syncthreads();

    if (wid >= 4) {
        // ================= PRODUCER (4 warps) =================
        const int ptid = tid - 128;
        const uint4* wv = reinterpret_cast<const uint4*>(w);
        const char* xsrc = reinterpret_cast<const char*>(g_x16);

        // Folded-swizzle STS base: row = (ptid>>4) + 8j, c = ptid&15 (const).
        const uint32_t sts0 = (uint32_t)(((ptid >> 4) * 128) +
                              (((ptid & 15) * 8) ^ ((((ptid >> 4) & 7)) << 4)));

        uint4 rb[2][8];
        #pragma unroll
        for (int j = 0; j < 8; j++) {                 // prefetch B for kt=0
            int idx = ptid + 128 * j;
            int row = idx >> 4, c = idx & 15;
            rb[0][j] = wv[(size_t)(n0 + row) * (K_DIM / 4) + c];
        }

        #pragma unroll 2
        for (int kt = 0; kt < NK; kt++) {
            const int s = kt & (STAGES - 1);
            const int r = kt >> 2;

            // hoist next B LDGs ABOVE the empty wait (latency overlap)
            if (kt + 1 < NK) {
                #pragma unroll
                for (int j = 0; j < 8; j++) {
                    int idx = ptid + 128 * j;
                    int row = idx >> 4, c = idx & 15;
                    rb[(kt + 1) & 1][j] =
                        wv[(size_t)(n0 + row) * (K_DIM / 4) + (size_t)(kt + 1) * (K_TILE / 4) + c];
                }
            }

            if (r >= 1)   // stage free when round r-1 consumers released it
                MBARRIER_WAIT_PARITY(sb + OFF_MBAR + s * 16 + 8, (r - 1) & 1);

            const uint32_t aB = sb + OFF_STG + s * STG_BYTES;
            // A: pre-swizzled gmem -> linear cp.async copy
            #pragma unroll
            for (int j = 0; j < 8; j++) {
                int idx = ptid + 128 * j;
                cp_async16(aB + (uint32_t)idx * 16,
                           xsrc + (size_t)kt * A_BYTES + (size_t)idx * 16);
            }
            CP_ASYNC_MBAR_ARRIVE(sb + OFF_MBAR + s * 16);   // self-balancing arrive

            // B: convert int32 -> fp16, STS at folded-swizzle addresses
            const uint32_t bS = aB + A_BYTES + sts0;
            #pragma unroll
            for (int j = 0; j < 8; j++) {
                const int* v = reinterpret_cast<const int*>(&rb[kt & 1][j]);
                __half2 h01 = __halves2half2(__int2half_rn(v[0]), __int2half_rn(v[1]));
                __half2 h23 = __halves2half2(__int2half_rn(v[2]), __int2half_rn(v[3]));
                uint2 pk;
                pk.x = *reinterpret_cast<const uint32_t*>(&h01);
                pk.y = *reinterpret_cast<const uint32_t*>(&h23);
                asm volatile("st.shared.v2.b32 [%0], {%1, %2};"
                             :: "r"(bS + (uint32_t)(j * 1024)), "r"(pk.x), "r"(pk.y) : "memory");
            }
            __syncwarp();
            if (lane == 0) MBARRIER_ARRIVE(sb + OFF_MBAR + s * 16);   // full (release)
        }
    } else {
        // ================= CONSUMER (4 warps, 2x2 grid of 64x32 tiles) =================
        const int warp_m = wid & 1, warp_n = wid >> 1;
        const int fr = lane & 15, fs = lane >> 4;

        // Folded swizzle: SW128(row*128 + x) = row*128 + (x ^ ((fr&7)<<4)).
        const uint32_t kmask = (uint32_t)((fr & 7) << 4);
        uint32_t koff[4];
        #pragma unroll
        for (int ks = 0; ks < 4; ks++)
            koff[ks] = ((uint32_t)(ks * 32 + fs * 16)) ^ kmask;
        const uint32_t aRow = (uint32_t)((warp_m * 64 + fr) * 128);   // + mt*2048
        const uint32_t bRow = (uint32_t)((warp_n * 32 + fr) * 128);   // + bt*2048

        float acc[4][4][4];
        #pragma unroll
        for (int i = 0; i < 4; i++)
            #pragma unroll
            for (int j = 0; j < 4; j++)
                #pragma unroll
                for (int k = 0; k < 4; k++) acc[i][j][k] = 0.0f;

        for (int kt = 0; kt < NK; kt++) {
            const int s = kt & (STAGES - 1);
            const int r = kt >> 2;
            MBARRIER_WAIT_PARITY(sb + OFF_MBAR + s * 16, r & 1);   // wait full (acquire)

            const uint32_t aB = sb + OFF_STG + s * STG_BYTES + aRow;
            const uint32_t bB = sb + OFF_STG + s * STG_BYTES + A_BYTES + bRow;

            // B-fragment pipeline: cold-load ks=0, prefetch ks+1 inside loop
            uint32_t b[2][2][4];
            #pragma unroll
            for (int bt = 0; bt < 2; bt++)
                ldsm_x4(b[0][bt][0], b[0][bt][1], b[0][bt][2], b[0][bt][3],
                        bB + koff[0] + bt * 2048);

            #pragma unroll
            for (int ks = 0; ks < 4; ks++) {
                const uint32_t aK = aB + koff[ks];
                uint32_t a[4][4];
                #pragma unroll
                for (int mt = 0; mt < 4; mt++)
                    ldsm_x4(a[mt][0], a[mt][1], a[mt][2], a[mt][3], aK + mt * 2048);
                if (ks < 3) {
                    #pragma unroll
                    for (int bt = 0; bt < 2; bt++)
                        ldsm_x4(b[(ks + 1) & 1][bt][0], b[(ks + 1) & 1][bt][1],
                                b[(ks + 1) & 1][bt][2], b[(ks + 1) & 1][bt][3],
                                bB + koff[ks + 1] + bt * 2048);
                }
                #pragma unroll
                for (int mt = 0; mt < 4; mt++)
                    #pragma unroll
                    for (int nt = 0; nt < 4; nt++) {
                        uint32_t bf[2] = { b[ks & 1][nt >> 1][nt & 1],
                                           b[ks & 1][nt >> 1][(nt & 1) + 2] };
                        mma16816(acc[mt][nt], a[mt], bf);
                    }
            }
            __syncwarp();
            if (lane == 0) MBARRIER_ARRIVE(sb + OFF_MBAR + s * 16 + 8);   // empty
        }

        // ---------------- epilogue ----------------
        const float sc  = *scale_p;
        const float zpv = *zp_p;
        const int qrow = lane >> 2;
        const int qcol = (lane & 3) * 2;
        const float* bs = reinterpret_cast<const float*>(smem + OFF_BIAS);

        #pragma unroll
        for (int mt = 0; mt < 4; mt++) {
            const int m0 = warp_m * 64 + mt * 16 + qrow;
            const float corr0 = sc * zpv * g_xsum[m0];
            const float corr8 = sc * zpv * g_xsum[m0 + 8];
            #pragma unroll
            for (int nt = 0; nt < 4; nt++) {
                const int n = warp_n * 32 + nt * 8 + qcol;
                const float b0 = bs[n], b1 = bs[n + 1];
                float2 v0, v1;
                v0.x = fmaf(sc, acc[mt][nt][0], b0 - corr0);
                v0.y = fmaf(sc, acc[mt][nt][1], b1 - corr0);
                v1.x = fmaf(sc, acc[mt][nt][2], b0 - corr8);
                v1.y = fmaf(sc, acc[mt][nt][3], b1 - corr8);
                *reinterpret_cast<float2*>(out + (size_t)m0 * N_OUT + n0 + n) = v0;
                *reinterpret_cast<float2*>(out + (size_t)(m0 + 8) * N_OUT + n0 + n) = v1;
            }
        }
    }
}

// ---------------- launch ----------------
extern "C" void kernel_launch(void* const* d_in, const int* in_sizes, int n_in,
                              void* d_out, int out_size) {
    (void)in_sizes; (void)n_in; (void)out_size;
    const float* x     = (const float*)d_in[0];
    const int*   w     = (const int*)  d_in[1];
    const float* scale = (const float*)d_in[2];
    const float* zp    = (const float*)d_in[3];
    const float* bias  = (const float*)d_in[4];
    float* out = (float*)d_out;

    cudaFuncSetAttribute(sqlin_gemm, cudaFuncAttributeMaxDynamicSharedMemorySize, SMEM_BYTES);

    sqlin_prep<<<M_TOK, 256>>>(x);

    // PDL launch: GEMM may begin launching while prep runs; its
    // griddepcontrol.wait enforces the data dependency.
    cudaLaunchConfig_t cfg = {};
    cfg.gridDim = dim3(N_OUT / N_TILE);
    cfg.blockDim = dim3(THREADS);
    cfg.dynamicSmemBytes = SMEM_BYTES;
    cfg.stream = 0;
    cudaLaunchAttribute attrs[1];
    attrs[0].id = cudaLaunchAttributeProgrammaticStreamSerialization;
    attrs[0].val.programmaticStreamSerializationAllowed = 1;
    cfg.attrs = attrs;
    cfg.numAttrs = 1;
    cudaLaunchKernelEx(&cfg, sqlin_gemm, w, scale, zp, bias, out);
}